// round 12
// baseline (speedup 1.0000x reference)
#include <cuda_runtime.h>
#include <cuda_fp16.h>
#include <stdint.h>
#include <math.h>

#define NN   50000
#define EE   800000
#define PP   3
#define INF_ 128
#define HH   8
#define DD   32
#define HD   256   // H*D
#define KTOT 768   // P*H*D
#define EMB  128
#define PN   (PP * NN)

// ---------------- scratch (static __device__; no allocations allowed) ---------
__device__ __half g_h16 [NN * INF_];      // h in fp16
__device__ __half g_fcwt[PP * HD * INF_]; // fc weights fp16, TRANSPOSED [p][n][k]
__device__ __half g_swt [EMB * KTOT];     // sem weights fp16, TRANSPOSED [n][k]
__device__ __half g_feat[PP * NN * HD];   // projected features (fp16)
__device__ __half g_outh[PP * NN * HD];   // per-metapath GAT output (fp16, post-ELU)
__device__ float  g_el  [PP * NN * HH];
__device__ float  g_er  [PP * NN * HH];
__device__ int    g_deg   [PN];
__device__ int    g_offs  [PN + 1];
__device__ int    g_cursor[PN];
__device__ int    g_srcl  [PP * EE];      // CSR-ordered src node ids

// ---------------- fp16 mma (m16n8k16, fp32 accum) ------------------------------
__device__ __forceinline__ void mma16(float* d, const uint32_t* a, const uint32_t* b) {
    asm volatile("mma.sync.aligned.m16n8k16.row.col.f32.f16.f16.f32 "
                 "{%0,%1,%2,%3},{%4,%5,%6,%7},{%8,%9},{%0,%1,%2,%3};"
                 : "+f"(d[0]), "+f"(d[1]), "+f"(d[2]), "+f"(d[3])
                 : "r"(a[0]), "r"(a[1]), "r"(a[2]), "r"(a[3]), "r"(b[0]), "r"(b[1]));
}

// ---------------- input conversions --------------------------------------------
__global__ void k_hconv(const float* __restrict__ hin) {
    int idx = blockIdx.x * 256 + threadIdx.x;   // one float4 each
    if (idx < NN * INF_ / 4) {
        float4 v = ((const float4*)hin)[idx];
        ((__half2*)g_h16)[idx * 2]     = __floats2half2_rn(v.x, v.y);
        ((__half2*)g_h16)[idx * 2 + 1] = __floats2half2_rn(v.z, v.w);
    }
}
// transpose-convert both weight matrices (coalesced read, strided fp16 write)
__global__ void k_wconvt(const float* __restrict__ fcw, const float* __restrict__ sw) {
    int idx = blockIdx.x * 256 + threadIdx.x;
    if (idx < PP * INF_ * HD) {              // fcw[p][k][n] -> g_fcwt[p][n][k]
        int n = idx & 255, pk = idx >> 8;
        int k = pk & 127, p = pk >> 7;
        g_fcwt[((p << 8) + n) * INF_ + k] = __float2half_rn(fcw[idx]);
    } else {
        int j = idx - PP * INF_ * HD;        // sw[k][n] -> g_swt[n][k]
        if (j < KTOT * EMB) {
            int n = j & 127, k = j >> 7;
            g_swt[n * KTOT + k] = __float2half_rn(sw[j]);
        }
    }
}

// ---------------- zero degree counters ----------------------------------------
__global__ void k_zero() {
    int idx = blockIdx.x * 256 + threadIdx.x;
    if (idx < PN) g_deg[idx] = 0;
}

// ---------------- feat = h @ W_p via fp16 MMA ---------------------------------
// CTA tile 32 rows x 128 cols (blockIdx.z = col half). 8 warps (2 m x 4 n),
// warp tile 16x32. Wt pre-transposed in global -> vectorized smem staging.
__global__ void k_feat()
{
    __shared__ __half Hs[32][136];
    __shared__ __half Wt[128][136];
    const int p  = blockIdx.y, ch = blockIdx.z;
    const int nb = blockIdx.x * 32;
    const int t  = threadIdx.x, warp = t >> 5, lane = t & 31;
    const int g  = lane >> 2, tg = lane & 3;
    const int rw = warp >> 2, cw = warp & 3;

    // Hs: 32 x 128 halfs = 512 uint4
    for (int i = t; i < 512; i += 256) {
        int r = i >> 4, q = i & 15;
        int row = nb + r;
        uint4 v = make_uint4(0u, 0u, 0u, 0u);
        if (row < NN) v = *(const uint4*)(g_h16 + (long)row * INF_ + q * 8);
        *(uint4*)&Hs[r][q * 8] = v;
    }
    // Wt: 128 n-rows x 128 k = 2048 uint4, vectorized from pre-transposed global
    const __half* Wbase = g_fcwt + ((p << 8) + ch * 128) * INF_;
    for (int i = t; i < 2048; i += 256) {
        int c = i >> 4, q = i & 15;
        *(uint4*)&Wt[c][q * 8] = *(const uint4*)(Wbase + c * INF_ + q * 8);
    }
    __syncthreads();

    float acc[4][4];
#pragma unroll
    for (int nt = 0; nt < 4; ++nt)
#pragma unroll
        for (int j = 0; j < 4; ++j) acc[nt][j] = 0.f;

#pragma unroll
    for (int ks = 0; ks < 8; ++ks) {
        const int k0 = ks * 16;
        uint32_t a[4];
        a[0] = *(const uint32_t*)&Hs[rw * 16 + g][k0 + 2 * tg];
        a[1] = *(const uint32_t*)&Hs[rw * 16 + 8 + g][k0 + 2 * tg];
        a[2] = *(const uint32_t*)&Hs[rw * 16 + g][k0 + 8 + 2 * tg];
        a[3] = *(const uint32_t*)&Hs[rw * 16 + 8 + g][k0 + 8 + 2 * tg];
#pragma unroll
        for (int nt = 0; nt < 4; ++nt) {
            const int bcol = cw * 32 + nt * 8 + g;
            uint32_t b[2];
            b[0] = *(const uint32_t*)&Wt[bcol][k0 + 2 * tg];
            b[1] = *(const uint32_t*)&Wt[bcol][k0 + 8 + 2 * tg];
            mma16(acc[nt], a, b);
        }
    }

    const int row0 = nb + rw * 16 + g, row1 = row0 + 8;
    __half* fp = g_feat + (long)p * NN * HD + ch * 128;
#pragma unroll
    for (int nt = 0; nt < 4; ++nt) {
        const int col = cw * 32 + nt * 8 + 2 * tg;
        if (row0 < NN)
            *(__half2*)(fp + (long)row0 * HD + col) = __floats2half2_rn(acc[nt][0], acc[nt][1]);
        if (row1 < NN)
            *(__half2*)(fp + (long)row1 * HD + col) = __floats2half2_rn(acc[nt][2], acc[nt][3]);
    }
}

// ---------------- el/er from fp16 feat ----------------------------------------
__global__ void k_elr(const float* __restrict__ al, const float* __restrict__ ar)
{
    const int wid = threadIdx.x >> 5, lane = threadIdx.x & 31;
    const int pn = blockIdx.x * 8 + wid;
    const int p  = pn / NN;
    const uint4 v = *((const uint4*)(g_feat + (long)pn * HD) + lane);
    const __half2* hv = (const __half2*)&v;
    const int head = lane >> 2, dbase = (lane & 3) * 8;
    const float* alp = al + p * HH * DD + head * DD + dbase;
    const float* arp = ar + p * HH * DD + head * DD + dbase;
    float sl = 0.f, sr = 0.f;
#pragma unroll
    for (int j = 0; j < 4; ++j) {
        float2 f = __half22float2(hv[j]);
        sl += f.x * alp[2 * j] + f.y * alp[2 * j + 1];
        sr += f.x * arp[2 * j] + f.y * arp[2 * j + 1];
    }
    sl += __shfl_xor_sync(0xffffffffu, sl, 1);
    sl += __shfl_xor_sync(0xffffffffu, sl, 2);
    sr += __shfl_xor_sync(0xffffffffu, sr, 1);
    sr += __shfl_xor_sync(0xffffffffu, sr, 2);
    if ((lane & 3) == 0) {
        g_el[pn * HH + head] = sl;
        g_er[pn * HH + head] = sr;
    }
}

// ---------------- CSR build ----------------------------------------------------
__global__ void k_hist(const int* __restrict__ ei) {
    const int p = blockIdx.y;
    const int e = blockIdx.x * 256 + threadIdx.x;
    const int dst = ei[p * 2 * EE + EE + e];
    atomicAdd(&g_deg[p * NN + dst], 1);
}

#define CHUNK 147   // ceil(150000 / 1024)
__global__ void k_scan() {
    __shared__ int s[1024];
    const int t = threadIdx.x;
    const int base = t * CHUNK;
    int sum = 0;
    for (int j = 0; j < CHUNK; ++j) {
        int idx = base + j;
        if (idx < PN) sum += g_deg[idx];
    }
    s[t] = sum;
    __syncthreads();
    for (int o = 1; o < 1024; o <<= 1) {
        int v = (t >= o) ? s[t - o] : 0;
        __syncthreads();
        s[t] += v;
        __syncthreads();
    }
    int run = (t > 0) ? s[t - 1] : 0;
    for (int j = 0; j < CHUNK; ++j) {
        int idx = base + j;
        if (idx < PN) {
            g_offs[idx]   = run;
            g_cursor[idx] = run;
            run += g_deg[idx];
        }
    }
    if (t == 1023) g_offs[PN] = s[1023];
}

__global__ void k_scatter(const int* __restrict__ ei) {
    const int p = blockIdx.y;
    const int e = blockIdx.x * 256 + threadIdx.x;
    const int src = ei[p * 2 * EE + e];
    const int dst = ei[p * 2 * EE + EE + e];
    int pos = atomicAdd(&g_cursor[p * NN + dst], 1);
    g_srcl[pos] = src;
}

// ---------------- per-dst gather-aggregate + softmax + ELU (fused) ------------
__global__ void k_agg(int p)
{
    const int wid  = threadIdx.x >> 5;
    const int lane = threadIdx.x & 31;
    const int n    = blockIdx.x * 8 + wid;
    const int pn   = p * NN + n;
    const int hh   = lane >> 2;
    const float er_h = g_er[pn * HH + hh];

    const int beg = g_offs[pn];
    const int end = g_offs[pn + 1];

    float a[8];
#pragma unroll
    for (int j = 0; j < 8; ++j) a[j] = 0.f;
    float den = 0.f;
    const uint4* fb = (const uint4*)g_feat;

    int i = beg;
    for (; i + 4 <= end; i += 4) {
        const int b0 = p * NN + __ldg(&g_srcl[i]);
        const int b1 = p * NN + __ldg(&g_srcl[i + 1]);
        const int b2 = p * NN + __ldg(&g_srcl[i + 2]);
        const int b3 = p * NN + __ldg(&g_srcl[i + 3]);
        const float x0 = __ldg(&g_el[b0 * HH + hh]);
        const float x1 = __ldg(&g_el[b1 * HH + hh]);
        const float x2 = __ldg(&g_el[b2 * HH + hh]);
        const float x3 = __ldg(&g_el[b3 * HH + hh]);
        const uint4 v0 = __ldg(&fb[b0 * 32 + lane]);
        const uint4 v1 = __ldg(&fb[b1 * 32 + lane]);
        const uint4 v2 = __ldg(&fb[b2 * 32 + lane]);
        const uint4 v3 = __ldg(&fb[b3 * 32 + lane]);
        float y0 = x0 + er_h, y1 = x1 + er_h, y2 = x2 + er_h, y3 = x3 + er_h;
        const float ex0 = __expf(fmaxf(y0, 0.2f * y0));
        const float ex1 = __expf(fmaxf(y1, 0.2f * y1));
        const float ex2 = __expf(fmaxf(y2, 0.2f * y2));
        const float ex3 = __expf(fmaxf(y3, 0.2f * y3));
        den += (ex0 + ex1) + (ex2 + ex3);
        const __half2* h0 = (const __half2*)&v0;
        const __half2* h1 = (const __half2*)&v1;
        const __half2* h2 = (const __half2*)&v2;
        const __half2* h3 = (const __half2*)&v3;
#pragma unroll
        for (int j = 0; j < 4; ++j) {
            float2 f0 = __half22float2(h0[j]);
            float2 f1 = __half22float2(h1[j]);
            float2 f2 = __half22float2(h2[j]);
            float2 f3 = __half22float2(h3[j]);
            a[2 * j]     = fmaf(ex0, f0.x, fmaf(ex1, f1.x, fmaf(ex2, f2.x, fmaf(ex3, f3.x, a[2 * j]))));
            a[2 * j + 1] = fmaf(ex0, f0.y, fmaf(ex1, f1.y, fmaf(ex2, f2.y, fmaf(ex3, f3.y, a[2 * j + 1]))));
        }
    }
    for (; i < end; ++i) {
        const int b0 = p * NN + __ldg(&g_srcl[i]);
        const float x0 = __ldg(&g_el[b0 * HH + hh]) + er_h;
        const uint4 v0 = __ldg(&fb[b0 * 32 + lane]);
        const float ex0 = __expf(fmaxf(x0, 0.2f * x0));
        den += ex0;
        const __half2* h0 = (const __half2*)&v0;
#pragma unroll
        for (int j = 0; j < 4; ++j) {
            float2 f0 = __half22float2(h0[j]);
            a[2 * j]     = fmaf(ex0, f0.x, a[2 * j]);
            a[2 * j + 1] = fmaf(ex0, f0.y, a[2 * j + 1]);
        }
    }

    const float inv = den > 0.f ? 1.f / den : 0.f;
#pragma unroll
    for (int j = 0; j < 8; ++j) {
        float v = a[j] * inv;
        a[j] = v > 0.f ? v : expm1f(v);
    }
    uint4 pk;
    __half2* ph = (__half2*)&pk;
    ph[0] = __floats2half2_rn(a[0], a[1]);
    ph[1] = __floats2half2_rn(a[2], a[3]);
    ph[2] = __floats2half2_rn(a[4], a[5]);
    ph[3] = __floats2half2_rn(a[6], a[7]);
    __stcs((uint4*)(g_outh + (long)pn * HD + lane * 8), pk);
}

// ---------------- final: out = z @ sem_w + sem_b via fp16 MMA -----------------
// CTA tile 128x128, K=768 in 24 chunks of 32. Wt pre-transposed -> uint4 staging.
__global__ void k_sem(const float* __restrict__ sb, float* __restrict__ out)
{
    __shared__ __half Zs[128][40];
    __shared__ __half Wt[128][40];
    const int nb = blockIdx.x * 128;
    const int t  = threadIdx.x, warp = t >> 5, lane = t & 31;
    const int g  = lane >> 2, tg = lane & 3;
    const int rw = warp >> 1, cw = warp & 1;

    float acc[2][8][4];
#pragma unroll
    for (int mt = 0; mt < 2; ++mt)
#pragma unroll
        for (int nt = 0; nt < 8; ++nt)
#pragma unroll
            for (int j = 0; j < 4; ++j) acc[mt][nt][j] = 0.f;

    for (int k0 = 0; k0 < KTOT; k0 += 32) {
        const int p  = k0 >> 8;
        const int c0 = k0 & 255;
        __syncthreads();
        // Zs: 128 rows x 32 halfs = 512 uint4
        for (int i = t; i < 512; i += 256) {
            int r = i >> 2, q = i & 3;
            int row = nb + r;
            uint4 v = make_uint4(0u, 0u, 0u, 0u);
            if (row < NN)
                v = __ldcs((const uint4*)(g_outh + ((long)p * NN + row) * HD + c0 + q * 8));
            *(uint4*)&Zs[r][q * 8] = v;
        }
        // Wt: 128 n-rows x 32 k = 512 uint4, from pre-transposed global
        for (int i = t; i < 512; i += 256) {
            int c = i >> 2, q = i & 3;
            *(uint4*)&Wt[c][q * 8] = *(const uint4*)(g_swt + (long)c * KTOT + k0 + q * 8);
        }
        __syncthreads();
#pragma unroll
        for (int ks = 0; ks < 2; ++ks) {
            const int kb = ks * 16;
            uint32_t a[2][4];
#pragma unroll
            for (int mt = 0; mt < 2; ++mt) {
                const int arow = rw * 32 + mt * 16 + g;
                a[mt][0] = *(const uint32_t*)&Zs[arow][kb + 2 * tg];
                a[mt][1] = *(const uint32_t*)&Zs[arow + 8][kb + 2 * tg];
                a[mt][2] = *(const uint32_t*)&Zs[arow][kb + 8 + 2 * tg];
                a[mt][3] = *(const uint32_t*)&Zs[arow + 8][kb + 8 + 2 * tg];
            }
#pragma unroll
            for (int nt = 0; nt < 8; ++nt) {
                const int bcol = cw * 64 + nt * 8 + g;
                uint32_t b[2];
                b[0] = *(const uint32_t*)&Wt[bcol][kb + 2 * tg];
                b[1] = *(const uint32_t*)&Wt[bcol][kb + 8 + 2 * tg];
                mma16(acc[0][nt], a[0], b);
                mma16(acc[1][nt], a[1], b);
            }
        }
    }

#pragma unroll
    for (int mt = 0; mt < 2; ++mt) {
        const int row0 = nb + rw * 32 + mt * 16 + g, row1 = row0 + 8;
#pragma unroll
        for (int nt = 0; nt < 8; ++nt) {
            const int col = cw * 64 + nt * 8 + 2 * tg;
            const float b0v = sb[col], b1v = sb[col + 1];
            if (row0 < NN) {
                out[(long)row0 * EMB + col]     = acc[mt][nt][0] + b0v;
                out[(long)row0 * EMB + col + 1] = acc[mt][nt][1] + b1v;
            }
            if (row1 < NN) {
                out[(long)row1 * EMB + col]     = acc[mt][nt][2] + b0v;
                out[(long)row1 * EMB + col + 1] = acc[mt][nt][3] + b1v;
            }
        }
    }
}

// ---------------- launch ------------------------------------------------------
extern "C" void kernel_launch(void* const* d_in, const int* in_sizes, int n_in,
                              void* d_out, int out_size)
{
    const float* h   = (const float*)d_in[0];
    const int*   ei  = (const int*)  d_in[1];
    const float* fcw = (const float*)d_in[2];
    const float* al  = (const float*)d_in[3];
    const float* ar  = (const float*)d_in[4];
    const float* sw  = (const float*)d_in[5];
    const float* sb  = (const float*)d_in[6];
    float* out = (float*)d_out;

    k_hconv  <<<NN * INF_ / 4 / 256, 256>>>(h);          // 1
    k_wconvt <<<768, 256>>>(fcw, sw);                    // 2
    k_zero   <<<(PN + 255) / 256, 256>>>();              // 3
    k_feat   <<<dim3((NN + 31) / 32, PP, 2), 256>>>();   // 4  <- profiled slot
    k_hist   <<<dim3(EE / 256, PP), 256>>>(ei);          // 5
    k_scan   <<<1, 1024>>>();                            // 6
    k_scatter<<<dim3(EE / 256, PP), 256>>>(ei);          // 7
    k_elr    <<<PN / 8, 256>>>(al, ar);                  // 8
    k_agg    <<<NN / 8, 256>>>(0);                       // 9
    k_agg    <<<NN / 8, 256>>>(1);                       // 10
    k_agg    <<<NN / 8, 256>>>(2);                       // 11
    k_sem    <<<(NN + 127) / 128, 256>>>(sb, out);       // 12
}

// round 13
// speedup vs baseline: 1.5102x; 1.5102x over previous
#include <cuda_runtime.h>
#include <cuda_fp16.h>
#include <stdint.h>
#include <math.h>

#define NN   50000
#define EE   800000
#define PP   3
#define INF_ 128
#define HH   8
#define DD   32
#define HD   256   // H*D
#define KTOT 768   // P*H*D
#define EMB  128
#define PN   (PP * NN)

// ---------------- scratch (static __device__; no allocations allowed) ---------
__device__ __half g_h16 [NN * INF_];      // h in fp16
__device__ __half g_fcwt[PP * HD * INF_]; // fc weights fp16, TRANSPOSED [p][n][k]
__device__ __half g_swt [EMB * KTOT];     // sem weights fp16, TRANSPOSED [n][k]
__device__ __half g_feat[PP * NN * HD];   // projected features (fp16)
__device__ __half g_outh[PP * NN * HD];   // per-metapath GAT output (fp16, post-ELU)
__device__ float  g_el  [PP * NN * HH];
__device__ float  g_er  [PP * NN * HH];
__device__ int    g_deg   [PN];
__device__ int    g_offs  [PN + 1];
__device__ int    g_cursor[PN];
__device__ int    g_srcl  [PP * EE];      // CSR-ordered src node ids

// ---------------- mma / ldmatrix helpers ---------------------------------------
__device__ __forceinline__ void mma16(float* d, const uint32_t* a, uint32_t b0, uint32_t b1) {
    asm volatile("mma.sync.aligned.m16n8k16.row.col.f32.f16.f16.f32 "
                 "{%0,%1,%2,%3},{%4,%5,%6,%7},{%8,%9},{%0,%1,%2,%3};"
                 : "+f"(d[0]), "+f"(d[1]), "+f"(d[2]), "+f"(d[3])
                 : "r"(a[0]), "r"(a[1]), "r"(a[2]), "r"(a[3]), "r"(b0), "r"(b1));
}
__device__ __forceinline__ uint32_t sm32(const void* p) {
    return (uint32_t)__cvta_generic_to_shared(p);
}
__device__ __forceinline__ void ldm4(uint32_t* r, uint32_t addr) {
    asm volatile("ldmatrix.sync.aligned.m8n8.x4.shared.b16 {%0,%1,%2,%3}, [%4];"
                 : "=r"(r[0]), "=r"(r[1]), "=r"(r[2]), "=r"(r[3]) : "r"(addr));
}

// ---------------- input conversions --------------------------------------------
__global__ void k_hconv(const float* __restrict__ hin) {
    int idx = blockIdx.x * 256 + threadIdx.x;   // one float4 each
    if (idx < NN * INF_ / 4) {
        float4 v = ((const float4*)hin)[idx];
        ((__half2*)g_h16)[idx * 2]     = __floats2half2_rn(v.x, v.y);
        ((__half2*)g_h16)[idx * 2 + 1] = __floats2half2_rn(v.z, v.w);
    }
}
// tiled transpose fcw[p][k=128][n=256] -> g_fcwt[p][n][k]  (coalesced both sides)
__global__ void k_wtr_fc(const float* __restrict__ fcw) {
    __shared__ __half s[32][33];
    const int n0 = blockIdx.x * 32, k0 = blockIdx.y * 32, p = blockIdx.z;
    const int tx = threadIdx.x & 31, ty4 = threadIdx.x >> 5;  // 32 x 8
#pragma unroll
    for (int j = 0; j < 4; ++j) {
        int k = k0 + ty4 * 4 + j;
        s[ty4 * 4 + j][tx] = __float2half_rn(fcw[(p * INF_ + k) * HD + n0 + tx]);
    }
    __syncthreads();
#pragma unroll
    for (int j = 0; j < 4; ++j) {
        int n = n0 + ty4 * 4 + j;
        g_fcwt[((p << 8) + n) * INF_ + k0 + tx] = s[tx][ty4 * 4 + j];
    }
}
// tiled transpose sw[k=768][n=128] -> g_swt[n][k]
__global__ void k_wtr_sw(const float* __restrict__ sw) {
    __shared__ __half s[32][33];
    const int n0 = blockIdx.x * 32, k0 = blockIdx.y * 32;
    const int tx = threadIdx.x & 31, ty4 = threadIdx.x >> 5;
#pragma unroll
    for (int j = 0; j < 4; ++j) {
        int k = k0 + ty4 * 4 + j;
        s[ty4 * 4 + j][tx] = __float2half_rn(sw[(long)k * EMB + n0 + tx]);
    }
    __syncthreads();
#pragma unroll
    for (int j = 0; j < 4; ++j) {
        int n = n0 + ty4 * 4 + j;
        g_swt[(long)n * KTOT + k0 + tx] = s[tx][ty4 * 4 + j];
    }
}

// ---------------- zero degree counters ----------------------------------------
__global__ void k_zero() {
    int idx = blockIdx.x * 256 + threadIdx.x;
    if (idx < PN) g_deg[idx] = 0;
}

// ---------------- feat = h @ W_p via fp16 MMA + ldmatrix ----------------------
// CTA tile 32 rows x 128 cols (blockIdx.z = col half). 8 warps (2 m x 4 n),
// warp tile 16x32. Frag loads via ldmatrix.x4 (3 LDSM per ks vs 12 LDS.32).
__global__ void k_feat()
{
    __shared__ __half Hs[32][136];
    __shared__ __half Wt[128][136];
    const int p  = blockIdx.y, ch = blockIdx.z;
    const int nb = blockIdx.x * 32;
    const int t  = threadIdx.x, warp = t >> 5, lane = t & 31;
    const int g  = lane >> 2, tg = lane & 3;
    const int rw = warp >> 2, cw = warp & 3;

    for (int i = t; i < 512; i += 256) {
        int r = i >> 4, q = i & 15;
        int row = nb + r;
        uint4 v = make_uint4(0u, 0u, 0u, 0u);
        if (row < NN) v = *(const uint4*)(g_h16 + (long)row * INF_ + q * 8);
        *(uint4*)&Hs[r][q * 8] = v;
    }
    const __half* Wbase = g_fcwt + ((p << 8) + ch * 128) * INF_;
    for (int i = t; i < 2048; i += 256) {
        int c = i >> 4, q = i & 15;
        *(uint4*)&Wt[c][q * 8] = *(const uint4*)(Wbase + c * INF_ + q * 8);
    }
    __syncthreads();

    float acc[4][4];
#pragma unroll
    for (int nt = 0; nt < 4; ++nt)
#pragma unroll
        for (int j = 0; j < 4; ++j) acc[nt][j] = 0.f;

    // ldmatrix lane address bases
    const int arow = rw * 16 + ((lane >> 3) & 1) * 8 + (lane & 7);
    const uint32_t a_base  = sm32(&Hs[arow][(lane >> 4) * 8]);
    const int bn  = ((lane >> 4) & 1) * 8 + (lane & 7);
    const uint32_t kbb = ((lane >> 3) & 1) * 8;
    const uint32_t b_base0 = sm32(&Wt[cw * 32 + bn][kbb]);
    const uint32_t b_base1 = sm32(&Wt[cw * 32 + 16 + bn][kbb]);

#pragma unroll
    for (int ks = 0; ks < 8; ++ks) {
        uint32_t a[4], b0[4], b1[4];
        ldm4(a,  a_base  + ks * 32);
        ldm4(b0, b_base0 + ks * 32);
        ldm4(b1, b_base1 + ks * 32);
        mma16(acc[0], a, b0[0], b0[1]);
        mma16(acc[1], a, b0[2], b0[3]);
        mma16(acc[2], a, b1[0], b1[1]);
        mma16(acc[3], a, b1[2], b1[3]);
    }

    const int row0 = nb + rw * 16 + g, row1 = row0 + 8;
    __half* fp = g_feat + (long)p * NN * HD + ch * 128;
#pragma unroll
    for (int nt = 0; nt < 4; ++nt) {
        const int col = cw * 32 + nt * 8 + 2 * tg;
        if (row0 < NN)
            *(__half2*)(fp + (long)row0 * HD + col) = __floats2half2_rn(acc[nt][0], acc[nt][1]);
        if (row1 < NN)
            *(__half2*)(fp + (long)row1 * HD + col) = __floats2half2_rn(acc[nt][2], acc[nt][3]);
    }
}

// ---------------- el/er from fp16 feat ----------------------------------------
__global__ void k_elr(const float* __restrict__ al, const float* __restrict__ ar)
{
    const int wid = threadIdx.x >> 5, lane = threadIdx.x & 31;
    const int pn = blockIdx.x * 8 + wid;
    const int p  = pn / NN;
    const uint4 v = *((const uint4*)(g_feat + (long)pn * HD) + lane);
    const __half2* hv = (const __half2*)&v;
    const int head = lane >> 2, dbase = (lane & 3) * 8;
    const float* alp = al + p * HH * DD + head * DD + dbase;
    const float* arp = ar + p * HH * DD + head * DD + dbase;
    float sl = 0.f, sr = 0.f;
#pragma unroll
    for (int j = 0; j < 4; ++j) {
        float2 f = __half22float2(hv[j]);
        sl += f.x * alp[2 * j] + f.y * alp[2 * j + 1];
        sr += f.x * arp[2 * j] + f.y * arp[2 * j + 1];
    }
    sl += __shfl_xor_sync(0xffffffffu, sl, 1);
    sl += __shfl_xor_sync(0xffffffffu, sl, 2);
    sr += __shfl_xor_sync(0xffffffffu, sr, 1);
    sr += __shfl_xor_sync(0xffffffffu, sr, 2);
    if ((lane & 3) == 0) {
        g_el[pn * HH + head] = sl;
        g_er[pn * HH + head] = sr;
    }
}

// ---------------- CSR build ----------------------------------------------------
__global__ void k_hist(const int* __restrict__ ei) {
    const int p = blockIdx.y;
    const int e = blockIdx.x * 256 + threadIdx.x;
    const int dst = ei[p * 2 * EE + EE + e];
    atomicAdd(&g_deg[p * NN + dst], 1);
}

#define CHUNK 147   // ceil(150000 / 1024)
__global__ void k_scan() {
    __shared__ int s[1024];
    const int t = threadIdx.x;
    const int base = t * CHUNK;
    int sum = 0;
    for (int j = 0; j < CHUNK; ++j) {
        int idx = base + j;
        if (idx < PN) sum += g_deg[idx];
    }
    s[t] = sum;
    __syncthreads();
    for (int o = 1; o < 1024; o <<= 1) {
        int v = (t >= o) ? s[t - o] : 0;
        __syncthreads();
        s[t] += v;
        __syncthreads();
    }
    int run = (t > 0) ? s[t - 1] : 0;
    for (int j = 0; j < CHUNK; ++j) {
        int idx = base + j;
        if (idx < PN) {
            g_offs[idx]   = run;
            g_cursor[idx] = run;
            run += g_deg[idx];
        }
    }
    if (t == 1023) g_offs[PN] = s[1023];
}

__global__ void k_scatter(const int* __restrict__ ei) {
    const int p = blockIdx.y;
    const int e = blockIdx.x * 256 + threadIdx.x;
    const int src = ei[p * 2 * EE + e];
    const int dst = ei[p * 2 * EE + EE + e];
    int pos = atomicAdd(&g_cursor[p * NN + dst], 1);
    g_srcl[pos] = src;
}

// ---------------- per-dst gather-aggregate + softmax + ELU (fused) ------------
__global__ void k_agg(int p)
{
    const int wid  = threadIdx.x >> 5;
    const int lane = threadIdx.x & 31;
    const int n    = blockIdx.x * 8 + wid;
    const int pn   = p * NN + n;
    const int hh   = lane >> 2;
    const float er_h = g_er[pn * HH + hh];

    const int beg = g_offs[pn];
    const int end = g_offs[pn + 1];

    float a[8];
#pragma unroll
    for (int j = 0; j < 8; ++j) a[j] = 0.f;
    float den = 0.f;
    const uint4* fb = (const uint4*)g_feat;

    int i = beg;
    for (; i + 4 <= end; i += 4) {
        const int b0 = p * NN + __ldg(&g_srcl[i]);
        const int b1 = p * NN + __ldg(&g_srcl[i + 1]);
        const int b2 = p * NN + __ldg(&g_srcl[i + 2]);
        const int b3 = p * NN + __ldg(&g_srcl[i + 3]);
        const float x0 = __ldg(&g_el[b0 * HH + hh]);
        const float x1 = __ldg(&g_el[b1 * HH + hh]);
        const float x2 = __ldg(&g_el[b2 * HH + hh]);
        const float x3 = __ldg(&g_el[b3 * HH + hh]);
        const uint4 v0 = __ldg(&fb[b0 * 32 + lane]);
        const uint4 v1 = __ldg(&fb[b1 * 32 + lane]);
        const uint4 v2 = __ldg(&fb[b2 * 32 + lane]);
        const uint4 v3 = __ldg(&fb[b3 * 32 + lane]);
        float y0 = x0 + er_h, y1 = x1 + er_h, y2 = x2 + er_h, y3 = x3 + er_h;
        const float ex0 = __expf(fmaxf(y0, 0.2f * y0));
        const float ex1 = __expf(fmaxf(y1, 0.2f * y1));
        const float ex2 = __expf(fmaxf(y2, 0.2f * y2));
        const float ex3 = __expf(fmaxf(y3, 0.2f * y3));
        den += (ex0 + ex1) + (ex2 + ex3);
        const __half2* h0 = (const __half2*)&v0;
        const __half2* h1 = (const __half2*)&v1;
        const __half2* h2 = (const __half2*)&v2;
        const __half2* h3 = (const __half2*)&v3;
#pragma unroll
        for (int j = 0; j < 4; ++j) {
            float2 f0 = __half22float2(h0[j]);
            float2 f1 = __half22float2(h1[j]);
            float2 f2 = __half22float2(h2[j]);
            float2 f3 = __half22float2(h3[j]);
            a[2 * j]     = fmaf(ex0, f0.x, fmaf(ex1, f1.x, fmaf(ex2, f2.x, fmaf(ex3, f3.x, a[2 * j]))));
            a[2 * j + 1] = fmaf(ex0, f0.y, fmaf(ex1, f1.y, fmaf(ex2, f2.y, fmaf(ex3, f3.y, a[2 * j + 1]))));
        }
    }
    for (; i < end; ++i) {
        const int b0 = p * NN + __ldg(&g_srcl[i]);
        const float x0 = __ldg(&g_el[b0 * HH + hh]) + er_h;
        const uint4 v0 = __ldg(&fb[b0 * 32 + lane]);
        const float ex0 = __expf(fmaxf(x0, 0.2f * x0));
        den += ex0;
        const __half2* h0 = (const __half2*)&v0;
#pragma unroll
        for (int j = 0; j < 4; ++j) {
            float2 f0 = __half22float2(h0[j]);
            a[2 * j]     = fmaf(ex0, f0.x, a[2 * j]);
            a[2 * j + 1] = fmaf(ex0, f0.y, a[2 * j + 1]);
        }
    }

    const float inv = den > 0.f ? 1.f / den : 0.f;
#pragma unroll
    for (int j = 0; j < 8; ++j) {
        float v = a[j] * inv;
        a[j] = v > 0.f ? v : expm1f(v);
    }
    uint4 pk;
    __half2* ph = (__half2*)&pk;
    ph[0] = __floats2half2_rn(a[0], a[1]);
    ph[1] = __floats2half2_rn(a[2], a[3]);
    ph[2] = __floats2half2_rn(a[4], a[5]);
    ph[3] = __floats2half2_rn(a[6], a[7]);
    __stcs((uint4*)(g_outh + (long)pn * HD + lane * 8), pk);
}

// ---------------- final: out = z @ sem_w + sem_b via fp16 MMA + ldmatrix ------
// CTA tile 128x128, K=768 in 24 chunks of 32. 8 warps (4x2), warp tile 32x64.
__global__ void k_sem(const float* __restrict__ sb, float* __restrict__ out)
{
    __shared__ __half Zs[128][40];
    __shared__ __half Wt[128][40];
    const int nb = blockIdx.x * 128;
    const int t  = threadIdx.x, warp = t >> 5, lane = t & 31;
    const int g  = lane >> 2, tg = lane & 3;
    const int rw = warp >> 1, cw = warp & 1;

    float acc[2][8][4];
#pragma unroll
    for (int mt = 0; mt < 2; ++mt)
#pragma unroll
        for (int nt = 0; nt < 8; ++nt)
#pragma unroll
            for (int j = 0; j < 4; ++j) acc[mt][nt][j] = 0.f;

    // ldmatrix lane bases (offsets within the 40-half rows)
    const int arow_l = ((lane >> 3) & 1) * 8 + (lane & 7);
    const uint32_t ka = (lane >> 4) * 8;
    const uint32_t a_base0 = sm32(&Zs[rw * 32 + arow_l][ka]);
    const uint32_t a_base1 = sm32(&Zs[rw * 32 + 16 + arow_l][ka]);
    const int bn = ((lane >> 4) & 1) * 8 + (lane & 7);
    const uint32_t kb = ((lane >> 3) & 1) * 8;
    uint32_t b_base[4];
#pragma unroll
    for (int q = 0; q < 4; ++q)
        b_base[q] = sm32(&Wt[cw * 64 + q * 16 + bn][kb]);

    for (int k0 = 0; k0 < KTOT; k0 += 32) {
        const int p  = k0 >> 8;
        const int c0 = k0 & 255;
        __syncthreads();
        for (int i = t; i < 512; i += 256) {
            int r = i >> 2, q = i & 3;
            int row = nb + r;
            uint4 v = make_uint4(0u, 0u, 0u, 0u);
            if (row < NN)
                v = __ldcs((const uint4*)(g_outh + ((long)p * NN + row) * HD + c0 + q * 8));
            *(uint4*)&Zs[r][q * 8] = v;
        }
        for (int i = t; i < 512; i += 256) {
            int c = i >> 2, q = i & 3;
            *(uint4*)&Wt[c][q * 8] = *(const uint4*)(g_swt + (long)c * KTOT + k0 + q * 8);
        }
        __syncthreads();
#pragma unroll
        for (int ks = 0; ks < 2; ++ks) {
            uint32_t a0[4], a1[4], bq[4][4];
            ldm4(a0, a_base0 + ks * 32);
            ldm4(a1, a_base1 + ks * 32);
#pragma unroll
            for (int q = 0; q < 4; ++q) ldm4(bq[q], b_base[q] + ks * 32);
#pragma unroll
            for (int q = 0; q < 4; ++q) {
                mma16(acc[0][2 * q],     a0, bq[q][0], bq[q][1]);
                mma16(acc[0][2 * q + 1], a0, bq[q][2], bq[q][3]);
                mma16(acc[1][2 * q],     a1, bq[q][0], bq[q][1]);
                mma16(acc[1][2 * q + 1], a1, bq[q][2], bq[q][3]);
            }
        }
    }

#pragma unroll
    for (int mt = 0; mt < 2; ++mt) {
        const int row0 = nb + rw * 32 + mt * 16 + g, row1 = row0 + 8;
#pragma unroll
        for (int nt = 0; nt < 8; ++nt) {
            const int col = cw * 64 + nt * 8 + 2 * tg;
            const float b0v = sb[col], b1v = sb[col + 1];
            if (row0 < NN) {
                out[(long)row0 * EMB + col]     = acc[mt][nt][0] + b0v;
                out[(long)row0 * EMB + col + 1] = acc[mt][nt][1] + b1v;
            }
            if (row1 < NN) {
                out[(long)row1 * EMB + col]     = acc[mt][nt][2] + b0v;
                out[(long)row1 * EMB + col + 1] = acc[mt][nt][3] + b1v;
            }
        }
    }
}

// ---------------- launch ------------------------------------------------------
extern "C" void kernel_launch(void* const* d_in, const int* in_sizes, int n_in,
                              void* d_out, int out_size)
{
    const float* h   = (const float*)d_in[0];
    const int*   ei  = (const int*)  d_in[1];
    const float* fcw = (const float*)d_in[2];
    const float* al  = (const float*)d_in[3];
    const float* ar  = (const float*)d_in[4];
    const float* sw  = (const float*)d_in[5];
    const float* sb  = (const float*)d_in[6];
    float* out = (float*)d_out;

    k_hconv  <<<NN * INF_ / 4 / 256, 256>>>(h);          // 1
    k_wtr_fc <<<dim3(HD / 32, INF_ / 32, PP), 256>>>(fcw); // 2
    k_wtr_sw <<<dim3(EMB / 32, KTOT / 32), 256>>>(sw);   // 3
    k_feat   <<<dim3((NN + 31) / 32, PP, 2), 256>>>();   // 4  <- profiled slot
    k_zero   <<<(PN + 255) / 256, 256>>>();              // 5
    k_hist   <<<dim3(EE / 256, PP), 256>>>(ei);          // 6
    k_scan   <<<1, 1024>>>();                            // 7
    k_scatter<<<dim3(EE / 256, PP), 256>>>(ei);          // 8
    k_elr    <<<PN / 8, 256>>>(al, ar);                  // 9
    k_agg    <<<NN / 8, 256>>>(0);                       // 10
    k_agg    <<<NN / 8, 256>>>(1);                       // 11
    k_agg    <<<NN / 8, 256>>>(2);                       // 12
    k_sem    <<<(NN + 127) / 128, 256>>>(sb, out);       // 13
}

// round 16
// speedup vs baseline: 1.7084x; 1.1312x over previous
#include <cuda_runtime.h>
#include <cuda_fp16.h>
#include <stdint.h>
#include <math.h>

#define NN   50000
#define EE   800000
#define PP   3
#define INF_ 128
#define HH   8
#define DD   32
#define HD   256   // H*D
#define KTOT 768   // P*H*D
#define EMB  128
#define PN   (PP * NN)
#define DEGPAD 151552   // 1024 threads * 148 (int4-aligned scan coverage)

// ---------------- scratch (static __device__; no allocations allowed) ---------
__device__ __half g_h16 [NN * INF_];      // h in fp16
__device__ __half g_fcwt[PP * HD * INF_]; // fc weights fp16, TRANSPOSED [p][n][k]
__device__ __half g_swt [EMB * KTOT];     // sem weights fp16, TRANSPOSED [n][k]
__device__ __half g_feat[PP * NN * HD];   // projected features (fp16)
__device__ __half g_outh[PP * NN * HD];   // per-metapath GAT output (fp16, post-ELU)
__device__ float  g_el  [PP * NN * HH];
__device__ float  g_er  [PP * NN * HH];
__device__ int    g_deg   [DEGPAD];       // padded so scan can read int4 past PN
__device__ int    g_offs  [PN + 1];
__device__ int    g_cursor[PN];
__device__ int    g_srcl  [PP * EE];      // CSR-ordered src node ids

// ---------------- mma / ldmatrix helpers ---------------------------------------
__device__ __forceinline__ void mma16(float* d, const uint32_t* a, uint32_t b0, uint32_t b1) {
    asm volatile("mma.sync.aligned.m16n8k16.row.col.f32.f16.f16.f32 "
                 "{%0,%1,%2,%3},{%4,%5,%6,%7},{%8,%9},{%0,%1,%2,%3};"
                 : "+f"(d[0]), "+f"(d[1]), "+f"(d[2]), "+f"(d[3])
                 : "r"(a[0]), "r"(a[1]), "r"(a[2]), "r"(a[3]), "r"(b0), "r"(b1));
}
__device__ __forceinline__ uint32_t sm32(const void* p) {
    return (uint32_t)__cvta_generic_to_shared(p);
}
__device__ __forceinline__ void ldm4(uint32_t* r, uint32_t addr) {
    asm volatile("ldmatrix.sync.aligned.m8n8.x4.shared.b16 {%0,%1,%2,%3}, [%4];"
                 : "=r"(r[0]), "=r"(r[1]), "=r"(r[2]), "=r"(r[3]) : "r"(addr));
}

// ---------------- fused conversions + deg zero (block-range partitioned) -------
// blocks [0,6250)          : h fp32 -> fp16
// blocks [6250,6346)       : fcw tiled transpose -> g_fcwt
// blocks [6346,6442)       : sw  tiled transpose -> g_swt
// blocks [6442,6590)       : zero g_deg (padded)
__global__ void k_conv(const float* __restrict__ hin, const float* __restrict__ fcw,
                       const float* __restrict__ sw)
{
    const int bid = blockIdx.x, t = threadIdx.x;
    if (bid < 6250) {
        int idx = bid * 256 + t;
        float4 v = ((const float4*)hin)[idx];
        ((__half2*)g_h16)[idx * 2]     = __floats2half2_rn(v.x, v.y);
        ((__half2*)g_h16)[idx * 2 + 1] = __floats2half2_rn(v.z, v.w);
    } else if (bid < 6346) {
        __shared__ __half s[32][33];
        const int b2 = bid - 6250;
        const int n0 = (b2 & 7) * 32, k0 = ((b2 >> 3) & 3) * 32, p = b2 >> 5;
        const int tx = t & 31, ty4 = t >> 5;
#pragma unroll
        for (int j = 0; j < 4; ++j) {
            int k = k0 + ty4 * 4 + j;
            s[ty4 * 4 + j][tx] = __float2half_rn(fcw[(p * INF_ + k) * HD + n0 + tx]);
        }
        __syncthreads();
#pragma unroll
        for (int j = 0; j < 4; ++j) {
            int n = n0 + ty4 * 4 + j;
            g_fcwt[((p << 8) + n) * INF_ + k0 + tx] = s[tx][ty4 * 4 + j];
        }
    } else if (bid < 6442) {
        __shared__ __half s[32][33];
        const int b3 = bid - 6346;
        const int n0 = (b3 & 3) * 32, k0 = (b3 >> 2) * 32;
        const int tx = t & 31, ty4 = t >> 5;
#pragma unroll
        for (int j = 0; j < 4; ++j) {
            int k = k0 + ty4 * 4 + j;
            s[ty4 * 4 + j][tx] = __float2half_rn(sw[(long)k * EMB + n0 + tx]);
        }
        __syncthreads();
#pragma unroll
        for (int j = 0; j < 4; ++j) {
            int n = n0 + ty4 * 4 + j;
            g_swt[(long)n * KTOT + k0 + tx] = s[tx][ty4 * 4 + j];
        }
    } else {
        int idx = (bid - 6442) * 256 + t;     // int4 index
        if (idx < DEGPAD / 4)
            ((int4*)g_deg)[idx] = make_int4(0, 0, 0, 0);
    }
}

// ---------------- feat = h @ W_p via fp16 MMA + ldmatrix ----------------------
// CTA: 128 rows x 128 cols as FOUR 32-row passes reusing one staged Wt.
// 8 warps (2 m x 4 n), warp tile 16x32.
__global__ void k_feat()
{
    __shared__ __half Hs[32][136];
    __shared__ __half Wt[128][136];
    const int p  = blockIdx.y, ch = blockIdx.z;
    const int nbb = blockIdx.x * 128;
    const int t  = threadIdx.x, warp = t >> 5, lane = t & 31;
    const int g  = lane >> 2, tg = lane & 3;
    const int rw = warp >> 2, cw = warp & 3;

    // Wt staged ONCE per CTA (synced by first in-loop barrier)
    const __half* Wbase = g_fcwt + ((p << 8) + ch * 128) * INF_;
    for (int i = t; i < 2048; i += 256) {
        int c = i >> 4, q = i & 15;
        *(uint4*)&Wt[c][q * 8] = *(const uint4*)(Wbase + c * INF_ + q * 8);
    }

    // ldmatrix lane address bases (fixed across passes)
    const int arow = rw * 16 + ((lane >> 3) & 1) * 8 + (lane & 7);
    const uint32_t a_base  = sm32(&Hs[arow][(lane >> 4) * 8]);
    const int bn  = ((lane >> 4) & 1) * 8 + (lane & 7);
    const uint32_t kbb = ((lane >> 3) & 1) * 8;
    const uint32_t b_base0 = sm32(&Wt[cw * 32 + bn][kbb]);
    const uint32_t b_base1 = sm32(&Wt[cw * 32 + 16 + bn][kbb]);

    __half* fp = g_feat + (long)p * NN * HD + ch * 128;

    for (int sb = 0; sb < 4; ++sb) {
        const int nb = nbb + sb * 32;
        __syncthreads();   // Wt ready (pass 0) / Hs no longer read (pass >0)
        for (int i = t; i < 512; i += 256) {
            int r = i >> 4, q = i & 15;
            int row = nb + r;
            uint4 v = make_uint4(0u, 0u, 0u, 0u);
            if (row < NN) v = *(const uint4*)(g_h16 + (long)row * INF_ + q * 8);
            *(uint4*)&Hs[r][q * 8] = v;
        }
        __syncthreads();

        float acc[4][4];
#pragma unroll
        for (int nt = 0; nt < 4; ++nt)
#pragma unroll
            for (int j = 0; j < 4; ++j) acc[nt][j] = 0.f;

#pragma unroll
        for (int ks = 0; ks < 8; ++ks) {
            uint32_t a[4], b0[4], b1[4];
            ldm4(a,  a_base  + ks * 32);
            ldm4(b0, b_base0 + ks * 32);
            ldm4(b1, b_base1 + ks * 32);
            mma16(acc[0], a, b0[0], b0[1]);
            mma16(acc[1], a, b0[2], b0[3]);
            mma16(acc[2], a, b1[0], b1[1]);
            mma16(acc[3], a, b1[2], b1[3]);
        }

        const int row0 = nb + rw * 16 + g, row1 = row0 + 8;
#pragma unroll
        for (int nt = 0; nt < 4; ++nt) {
            const int col = cw * 32 + nt * 8 + 2 * tg;
            if (row0 < NN)
                *(__half2*)(fp + (long)row0 * HD + col) = __floats2half2_rn(acc[nt][0], acc[nt][1]);
            if (row1 < NN)
                *(__half2*)(fp + (long)row1 * HD + col) = __floats2half2_rn(acc[nt][2], acc[nt][3]);
        }
    }
}

// ---------------- el/er from fp16 feat ----------------------------------------
__global__ void k_elr(const float* __restrict__ al, const float* __restrict__ ar)
{
    const int wid = threadIdx.x >> 5, lane = threadIdx.x & 31;
    const int pn = blockIdx.x * 8 + wid;
    const int p  = pn / NN;
    const uint4 v = *((const uint4*)(g_feat + (long)pn * HD) + lane);
    const __half2* hv = (const __half2*)&v;
    const int head = lane >> 2, dbase = (lane & 3) * 8;
    const float* alp = al + p * HH * DD + head * DD + dbase;
    const float* arp = ar + p * HH * DD + head * DD + dbase;
    float sl = 0.f, sr = 0.f;
#pragma unroll
    for (int j = 0; j < 4; ++j) {
        float2 f = __half22float2(hv[j]);
        sl += f.x * alp[2 * j] + f.y * alp[2 * j + 1];
        sr += f.x * arp[2 * j] + f.y * arp[2 * j + 1];
    }
    sl += __shfl_xor_sync(0xffffffffu, sl, 1);
    sl += __shfl_xor_sync(0xffffffffu, sl, 2);
    sr += __shfl_xor_sync(0xffffffffu, sr, 1);
    sr += __shfl_xor_sync(0xffffffffu, sr, 2);
    if ((lane & 3) == 0) {
        g_el[pn * HH + head] = sl;
        g_er[pn * HH + head] = sr;
    }
}

// ---------------- CSR build ----------------------------------------------------
__global__ void k_hist(const int* __restrict__ ei) {
    const int p = blockIdx.y;
    const int e = blockIdx.x * 256 + threadIdx.x;
    const int dst = ei[p * 2 * EE + EE + e];
    atomicAdd(&g_deg[p * NN + dst], 1);
}

// single-block scan, int4-vectorized load/write phases (37 int4 = 148 ints/thread)
__global__ void k_scan() {
    __shared__ int s[1024];
    const int t = threadIdx.x;
    const int base4 = t * 37;            // int4 index base
    int sum = 0;
#pragma unroll 4
    for (int j = 0; j < 37; ++j) {
        int4 v = ((const int4*)g_deg)[base4 + j];
        sum += v.x + v.y + v.z + v.w;
    }
    s[t] = sum;
    __syncthreads();
    for (int o = 1; o < 1024; o <<= 1) {
        int v = (t >= o) ? s[t - o] : 0;
        __syncthreads();
        s[t] += v;
        __syncthreads();
    }
    int run = (t > 0) ? s[t - 1] : 0;
    const int base = base4 * 4;
    for (int j = 0; j < 37; ++j) {
        int4 v = ((const int4*)g_deg)[base4 + j];
        int idx = base + j * 4;
        if (idx < PN)     { g_offs[idx]     = run; g_cursor[idx]     = run; } run += v.x;
        if (idx + 1 < PN) { g_offs[idx + 1] = run; g_cursor[idx + 1] = run; } run += v.y;
        if (idx + 2 < PN) { g_offs[idx + 2] = run; g_cursor[idx + 2] = run; } run += v.z;
        if (idx + 3 < PN) { g_offs[idx + 3] = run; g_cursor[idx + 3] = run; } run += v.w;
    }
    if (t == 1023) g_offs[PN] = s[1023];
}

__global__ void k_scatter(const int* __restrict__ ei) {
    const int p = blockIdx.y;
    const int e = blockIdx.x * 256 + threadIdx.x;
    const int src = ei[p * 2 * EE + e];
    const int dst = ei[p * 2 * EE + EE + e];
    int pos = atomicAdd(&g_cursor[p * NN + dst], 1);
    g_srcl[pos] = src;
}

// ---------------- per-dst gather-aggregate + softmax + ELU (fused) ------------
__global__ void k_agg()
{
    const int p    = blockIdx.y;
    const int wid  = threadIdx.x >> 5;
    const int lane = threadIdx.x & 31;
    const int n    = blockIdx.x * 8 + wid;
    const int pn   = p * NN + n;
    const int hh   = lane >> 2;
    const float er_h = g_er[pn * HH + hh];

    const int beg = g_offs[pn];
    const int end = g_offs[pn + 1];

    float a[8];
#pragma unroll
    for (int j = 0; j < 8; ++j) a[j] = 0.f;
    float den = 0.f;
    const uint4* fb = (const uint4*)g_feat;

    int i = beg;
    for (; i + 4 <= end; i += 4) {
        const int b0 = p * NN + __ldg(&g_srcl[i]);
        const int b1 = p * NN + __ldg(&g_srcl[i + 1]);
        const int b2 = p * NN + __ldg(&g_srcl[i + 2]);
        const int b3 = p * NN + __ldg(&g_srcl[i + 3]);
        const float x0 = __ldg(&g_el[b0 * HH + hh]);
        const float x1 = __ldg(&g_el[b1 * HH + hh]);
        const float x2 = __ldg(&g_el[b2 * HH + hh]);
        const float x3 = __ldg(&g_el[b3 * HH + hh]);
        const uint4 v0 = __ldg(&fb[b0 * 32 + lane]);
        const uint4 v1 = __ldg(&fb[b1 * 32 + lane]);
        const uint4 v2 = __ldg(&fb[b2 * 32 + lane]);
        const uint4 v3 = __ldg(&fb[b3 * 32 + lane]);
        float y0 = x0 + er_h, y1 = x1 + er_h, y2 = x2 + er_h, y3 = x3 + er_h;
        const float ex0 = __expf(fmaxf(y0, 0.2f * y0));
        const float ex1 = __expf(fmaxf(y1, 0.2f * y1));
        const float ex2 = __expf(fmaxf(y2, 0.2f * y2));
        const float ex3 = __expf(fmaxf(y3, 0.2f * y3));
        den += (ex0 + ex1) + (ex2 + ex3);
        const __half2* h0 = (const __half2*)&v0;
        const __half2* h1 = (const __half2*)&v1;
        const __half2* h2 = (const __half2*)&v2;
        const __half2* h3 = (const __half2*)&v3;
#pragma unroll
        for (int j = 0; j < 4; ++j) {
            float2 f0 = __half22float2(h0[j]);
            float2 f1 = __half22float2(h1[j]);
            float2 f2 = __half22float2(h2[j]);
            float2 f3 = __half22float2(h3[j]);
            a[2 * j]     = fmaf(ex0, f0.x, fmaf(ex1, f1.x, fmaf(ex2, f2.x, fmaf(ex3, f3.x, a[2 * j]))));
            a[2 * j + 1] = fmaf(ex0, f0.y, fmaf(ex1, f1.y, fmaf(ex2, f2.y, fmaf(ex3, f3.y, a[2 * j + 1]))));
        }
    }
    for (; i < end; ++i) {
        const int b0 = p * NN + __ldg(&g_srcl[i]);
        const float x0 = __ldg(&g_el[b0 * HH + hh]) + er_h;
        const uint4 v0 = __ldg(&fb[b0 * 32 + lane]);
        const float ex0 = __expf(fmaxf(x0, 0.2f * x0));
        den += ex0;
        const __half2* h0 = (const __half2*)&v0;
#pragma unroll
        for (int j = 0; j < 4; ++j) {
            float2 f0 = __half22float2(h0[j]);
            a[2 * j]     = fmaf(ex0, f0.x, a[2 * j]);
            a[2 * j + 1] = fmaf(ex0, f0.y, a[2 * j + 1]);
        }
    }

    const float inv = den > 0.f ? 1.f / den : 0.f;
#pragma unroll
    for (int j = 0; j < 8; ++j) {
        float v = a[j] * inv;
        a[j] = v > 0.f ? v : expm1f(v);
    }
    uint4 pk;
    __half2* ph = (__half2*)&pk;
    ph[0] = __floats2half2_rn(a[0], a[1]);
    ph[1] = __floats2half2_rn(a[2], a[3]);
    ph[2] = __floats2half2_rn(a[4], a[5]);
    ph[3] = __floats2half2_rn(a[6], a[7]);
    __stcs((uint4*)(g_outh + (long)pn * HD + lane * 8), pk);
}

// ---------------- final: out = z @ sem_w + sem_b via fp16 MMA + ldmatrix ------
__global__ void k_sem(const float* __restrict__ sb, float* __restrict__ out)
{
    __shared__ __half Zs[128][40];
    __shared__ __half Wt[128][40];
    const int nb = blockIdx.x * 128;
    const int t  = threadIdx.x, warp = t >> 5, lane = t & 31;
    const int g  = lane >> 2, tg = lane & 3;
    const int rw = warp >> 1, cw = warp & 1;

    float acc[2][8][4];
#pragma unroll
    for (int mt = 0; mt < 2; ++mt)
#pragma unroll
        for (int nt = 0; nt < 8; ++nt)
#pragma unroll
            for (int j = 0; j < 4; ++j) acc[mt][nt][j] = 0.f;

    const int arow_l = ((lane >> 3) & 1) * 8 + (lane & 7);
    const uint32_t ka = (lane >> 4) * 8;
    const uint32_t a_base0 = sm32(&Zs[rw * 32 + arow_l][ka]);
    const uint32_t a_base1 = sm32(&Zs[rw * 32 + 16 + arow_l][ka]);
    const int bn = ((lane >> 4) & 1) * 8 + (lane & 7);
    const uint32_t kb = ((lane >> 3) & 1) * 8;
    uint32_t b_base[4];
#pragma unroll
    for (int q = 0; q < 4; ++q)
        b_base[q] = sm32(&Wt[cw * 64 + q * 16 + bn][kb]);

    for (int k0 = 0; k0 < KTOT; k0 += 32) {
        const int p  = k0 >> 8;
        const int c0 = k0 & 255;
        __syncthreads();
        for (int i = t; i < 512; i += 256) {
            int r = i >> 2, q = i & 3;
            int row = nb + r;
            uint4 v = make_uint4(0u, 0u, 0u, 0u);
            if (row < NN)
                v = __ldcs((const uint4*)(g_outh + ((long)p * NN + row) * HD + c0 + q * 8));
            *(uint4*)&Zs[r][q * 8] = v;
        }
        for (int i = t; i < 512; i += 256) {
            int c = i >> 2, q = i & 3;
            *(uint4*)&Wt[c][q * 8] = *(const uint4*)(g_swt + (long)c * KTOT + k0 + q * 8);
        }
        __syncthreads();
#pragma unroll
        for (int ks = 0; ks < 2; ++ks) {
            uint32_t a0[4], a1[4], bq[4][4];
            ldm4(a0, a_base0 + ks * 32);
            ldm4(a1, a_base1 + ks * 32);
#pragma unroll
            for (int q = 0; q < 4; ++q) ldm4(bq[q], b_base[q] + ks * 32);
#pragma unroll
            for (int q = 0; q < 4; ++q) {
                mma16(acc[0][2 * q],     a0, bq[q][0], bq[q][1]);
                mma16(acc[0][2 * q + 1], a0, bq[q][2], bq[q][3]);
                mma16(acc[1][2 * q],     a1, bq[q][0], bq[q][1]);
                mma16(acc[1][2 * q + 1], a1, bq[q][2], bq[q][3]);
            }
        }
    }

#pragma unroll
    for (int mt = 0; mt < 2; ++mt) {
        const int row0 = nb + rw * 32 + mt * 16 + g, row1 = row0 + 8;
#pragma unroll
        for (int nt = 0; nt < 8; ++nt) {
            const int col = cw * 64 + nt * 8 + 2 * tg;
            const float b0v = sb[col], b1v = sb[col + 1];
            if (row0 < NN) {
                out[(long)row0 * EMB + col]     = acc[mt][nt][0] + b0v;
                out[(long)row0 * EMB + col + 1] = acc[mt][nt][1] + b1v;
            }
            if (row1 < NN) {
                out[(long)row1 * EMB + col]     = acc[mt][nt][2] + b0v;
                out[(long)row1 * EMB + col + 1] = acc[mt][nt][3] + b1v;
            }
        }
    }
}

// ---------------- launch ------------------------------------------------------
extern "C" void kernel_launch(void* const* d_in, const int* in_sizes, int n_in,
                              void* d_out, int out_size)
{
    const float* h   = (const float*)d_in[0];
    const int*   ei  = (const int*)  d_in[1];
    const float* fcw = (const float*)d_in[2];
    const float* al  = (const float*)d_in[3];
    const float* ar  = (const float*)d_in[4];
    const float* sw  = (const float*)d_in[5];
    const float* sb  = (const float*)d_in[6];
    float* out = (float*)d_out;

    k_conv   <<<6590, 256>>>(h, fcw, sw);                  // 1
    k_feat   <<<dim3((NN + 127) / 128, PP, 2), 256>>>();   // 2
    k_elr    <<<PN / 8, 256>>>(al, ar);                    // 3
    k_hist   <<<dim3(EE / 256, PP), 256>>>(ei);            // 4  <- profiled slot
    k_scan   <<<1, 1024>>>();                              // 5
    k_scatter<<<dim3(EE / 256, PP), 256>>>(ei);            // 6
    k_agg    <<<dim3(NN / 8, PP), 256>>>();                // 7
    k_sem    <<<(NN + 127) / 128, 256>>>(sb, out);         // 8
}

// round 17
// speedup vs baseline: 2.0658x; 1.2092x over previous
#include <cuda_runtime.h>
#include <cuda_fp16.h>
#include <stdint.h>
#include <math.h>

#define NN   50000
#define EE   800000
#define PP   3
#define INF_ 128
#define HH   8
#define DD   32
#define HD   256   // H*D
#define KTOT 768   // P*H*D
#define EMB  128
#define PN   (PP * NN)
#define DEGPAD 151552   // int4-aligned zero coverage >= PN
#define MAXDEG 64

// ---------------- scratch (static __device__; no allocations allowed) ---------
__device__ __half g_swt [EMB * KTOT];     // sem weights fp16, TRANSPOSED [n][k]
__device__ __half g_feat[PP * NN * HD];   // projected features (fp16)
__device__ __half g_outh[PP * NN * HD];   // per-metapath GAT output (fp16, post-ELU)
__device__ float  g_el  [PP * NN * HH];
__device__ float  g_er  [PP * NN * HH];
__device__ int    g_deg [DEGPAD];
__device__ int    g_srcp[PN * MAXDEG + MAXDEG];  // padded per-dst src buckets

// ---------------- mma / ldmatrix helpers ---------------------------------------
__device__ __forceinline__ void mma16(float* d, const uint32_t* a, uint32_t b0, uint32_t b1) {
    asm volatile("mma.sync.aligned.m16n8k16.row.col.f32.f16.f16.f32 "
                 "{%0,%1,%2,%3},{%4,%5,%6,%7},{%8,%9},{%0,%1,%2,%3};"
                 : "+f"(d[0]), "+f"(d[1]), "+f"(d[2]), "+f"(d[3])
                 : "r"(a[0]), "r"(a[1]), "r"(a[2]), "r"(a[3]), "r"(b0), "r"(b1));
}
__device__ __forceinline__ uint32_t sm32(const void* p) {
    return (uint32_t)__cvta_generic_to_shared(p);
}
__device__ __forceinline__ void ldm4(uint32_t* r, uint32_t addr) {
    asm volatile("ldmatrix.sync.aligned.m8n8.x4.shared.b16 {%0,%1,%2,%3}, [%4];"
                 : "=r"(r[0]), "=r"(r[1]), "=r"(r[2]), "=r"(r[3]) : "r"(addr));
}

// ---------------- feat = h @ W_p via fp16 MMA, fp32 inputs inline-converted ----
// blocks [0,2346): feat. CTA: 128 rows x 128 cols in four 32-row passes.
// blocks [2346,2442): sw tiled transpose -> g_swt
// blocks [2442,2590): zero g_deg
__global__ void k_feat(const float* __restrict__ hin, const float* __restrict__ fcw,
                       const float* __restrict__ sw)
{
    const int bid = blockIdx.x, t = threadIdx.x;

    if (bid >= 2346) {
        if (bid < 2442) {                 // sw transpose: 24 k-tiles x 4 n-tiles
            __shared__ __half s[32][33];
            const int b3 = bid - 2346;
            const int n0 = (b3 & 3) * 32, k0 = (b3 >> 2) * 32;
            const int tx = t & 31, ty4 = t >> 5;
#pragma unroll
            for (int j = 0; j < 4; ++j) {
                int k = k0 + ty4 * 4 + j;
                s[ty4 * 4 + j][tx] = __float2half_rn(sw[(long)k * EMB + n0 + tx]);
            }
            __syncthreads();
#pragma unroll
            for (int j = 0; j < 4; ++j) {
                int n = n0 + ty4 * 4 + j;
                g_swt[(long)n * KTOT + k0 + tx] = s[tx][ty4 * 4 + j];
            }
        } else {                          // zero g_deg
            int idx = (bid - 2442) * 256 + t;
            if (idx < DEGPAD / 4)
                ((int4*)g_deg)[idx] = make_int4(0, 0, 0, 0);
        }
        return;
    }

    __shared__ __half Hs[32][136];
    __shared__ __half Wt[128][136];
    const int p  = bid / 782;
    const int r2 = bid % 782;
    const int ch = r2 / 391;
    const int nbb = (r2 % 391) * 128;
    const int warp = t >> 5, lane = t & 31;
    const int g  = lane >> 2, tg = lane & 3;
    const int rw = warp >> 2, cw = warp & 3;

    // Wt staged ONCE per CTA from fp32 fcw, transposed+converted inline
    const float* Wbase = fcw + (long)p * INF_ * HD + ch * 128;
    for (int i = t; i < 4096; i += 256) {
        int k = i >> 5, c4 = i & 31;
        float4 wv = *(const float4*)(Wbase + (long)k * HD + c4 * 4);
        Wt[c4 * 4 + 0][k] = __float2half_rn(wv.x);
        Wt[c4 * 4 + 1][k] = __float2half_rn(wv.y);
        Wt[c4 * 4 + 2][k] = __float2half_rn(wv.z);
        Wt[c4 * 4 + 3][k] = __float2half_rn(wv.w);
    }

    const int arow = rw * 16 + ((lane >> 3) & 1) * 8 + (lane & 7);
    const uint32_t a_base  = sm32(&Hs[arow][(lane >> 4) * 8]);
    const int bn  = ((lane >> 4) & 1) * 8 + (lane & 7);
    const uint32_t kbb = ((lane >> 3) & 1) * 8;
    const uint32_t b_base0 = sm32(&Wt[cw * 32 + bn][kbb]);
    const uint32_t b_base1 = sm32(&Wt[cw * 32 + 16 + bn][kbb]);

    __half* fp = g_feat + (long)p * NN * HD + ch * 128;

    for (int sb = 0; sb < 4; ++sb) {
        const int nb = nbb + sb * 32;
        __syncthreads();
        for (int i = t; i < 1024; i += 256) {
            int r = i >> 5, q4 = i & 31;
            int row = nb + r;
            float4 v = make_float4(0.f, 0.f, 0.f, 0.f);
            if (row < NN) v = *(const float4*)(hin + (long)row * INF_ + q4 * 4);
            __half2 h0 = __floats2half2_rn(v.x, v.y);
            __half2 h1 = __floats2half2_rn(v.z, v.w);
            uint2 pk = make_uint2(*(uint32_t*)&h0, *(uint32_t*)&h1);
            *(uint2*)&Hs[r][q4 * 4] = pk;
        }
        __syncthreads();

        float acc[4][4];
#pragma unroll
        for (int nt = 0; nt < 4; ++nt)
#pragma unroll
            for (int j = 0; j < 4; ++j) acc[nt][j] = 0.f;

#pragma unroll
        for (int ks = 0; ks < 8; ++ks) {
            uint32_t a[4], b0[4], b1[4];
            ldm4(a,  a_base  + ks * 32);
            ldm4(b0, b_base0 + ks * 32);
            ldm4(b1, b_base1 + ks * 32);
            mma16(acc[0], a, b0[0], b0[1]);
            mma16(acc[1], a, b0[2], b0[3]);
            mma16(acc[2], a, b1[0], b1[1]);
            mma16(acc[3], a, b1[2], b1[3]);
        }

        const int row0 = nb + rw * 16 + g, row1 = row0 + 8;
#pragma unroll
        for (int nt = 0; nt < 4; ++nt) {
            const int col = cw * 32 + nt * 8 + 2 * tg;
            if (row0 < NN)
                *(__half2*)(fp + (long)row0 * HD + col) = __floats2half2_rn(acc[nt][0], acc[nt][1]);
            if (row1 < NN)
                *(__half2*)(fp + (long)row1 * HD + col) = __floats2half2_rn(acc[nt][2], acc[nt][3]);
        }
    }
}

// ---------------- single-pass bucket scatter (replaces hist+scan+scatter) -----
__global__ void k_hscat(const int* __restrict__ ei) {
    const int p = blockIdx.y;
    const int e = blockIdx.x * 256 + threadIdx.x;
    const int src = ei[p * 2 * EE + e];
    const int dst = ei[p * 2 * EE + EE + e];
    const int pn  = p * NN + dst;
    int pos = atomicAdd(&g_deg[pn], 1) & (MAXDEG - 1);
    g_srcp[pn * MAXDEG + pos] = src;
}

// ---------------- el/er from fp16 feat ----------------------------------------
__global__ void k_elr(const float* __restrict__ al, const float* __restrict__ ar)
{
    const int wid = threadIdx.x >> 5, lane = threadIdx.x & 31;
    const int pn = blockIdx.x * 8 + wid;
    const int p  = pn / NN;
    const uint4 v = *((const uint4*)(g_feat + (long)pn * HD) + lane);
    const __half2* hv = (const __half2*)&v;
    const int head = lane >> 2, dbase = (lane & 3) * 8;
    const float* alp = al + p * HH * DD + head * DD + dbase;
    const float* arp = ar + p * HH * DD + head * DD + dbase;
    float sl = 0.f, sr = 0.f;
#pragma unroll
    for (int j = 0; j < 4; ++j) {
        float2 f = __half22float2(hv[j]);
        sl += f.x * alp[2 * j] + f.y * alp[2 * j + 1];
        sr += f.x * arp[2 * j] + f.y * arp[2 * j + 1];
    }
    sl += __shfl_xor_sync(0xffffffffu, sl, 1);
    sl += __shfl_xor_sync(0xffffffffu, sl, 2);
    sr += __shfl_xor_sync(0xffffffffu, sr, 1);
    sr += __shfl_xor_sync(0xffffffffu, sr, 2);
    if ((lane & 3) == 0) {
        g_el[pn * HH + head] = sl;
        g_er[pn * HH + head] = sr;
    }
}

// ---------------- per-dst gather-aggregate + softmax + ELU (fused) ------------
__global__ void k_agg()
{
    const int p    = blockIdx.y;
    const int wid  = threadIdx.x >> 5;
    const int lane = threadIdx.x & 31;
    const int n    = blockIdx.x * 8 + wid;
    const int pn   = p * NN + n;
    const int hh   = lane >> 2;
    const float er_h = g_er[pn * HH + hh];

    const int deg  = min(g_deg[pn], MAXDEG);
    const int* sp  = g_srcp + pn * MAXDEG;

    float a[8];
#pragma unroll
    for (int j = 0; j < 8; ++j) a[j] = 0.f;
    float den = 0.f;
    const uint4* fb = (const uint4*)g_feat;

    int i = 0;
    for (; i + 4 <= deg; i += 4) {
        const int b0 = p * NN + __ldg(&sp[i]);
        const int b1 = p * NN + __ldg(&sp[i + 1]);
        const int b2 = p * NN + __ldg(&sp[i + 2]);
        const int b3 = p * NN + __ldg(&sp[i + 3]);
        const float x0 = __ldg(&g_el[b0 * HH + hh]);
        const float x1 = __ldg(&g_el[b1 * HH + hh]);
        const float x2 = __ldg(&g_el[b2 * HH + hh]);
        const float x3 = __ldg(&g_el[b3 * HH + hh]);
        const uint4 v0 = __ldg(&fb[b0 * 32 + lane]);
        const uint4 v1 = __ldg(&fb[b1 * 32 + lane]);
        const uint4 v2 = __ldg(&fb[b2 * 32 + lane]);
        const uint4 v3 = __ldg(&fb[b3 * 32 + lane]);
        float y0 = x0 + er_h, y1 = x1 + er_h, y2 = x2 + er_h, y3 = x3 + er_h;
        const float ex0 = __expf(fmaxf(y0, 0.2f * y0));
        const float ex1 = __expf(fmaxf(y1, 0.2f * y1));
        const float ex2 = __expf(fmaxf(y2, 0.2f * y2));
        const float ex3 = __expf(fmaxf(y3, 0.2f * y3));
        den += (ex0 + ex1) + (ex2 + ex3);
        const __half2* h0 = (const __half2*)&v0;
        const __half2* h1 = (const __half2*)&v1;
        const __half2* h2 = (const __half2*)&v2;
        const __half2* h3 = (const __half2*)&v3;
#pragma unroll
        for (int j = 0; j < 4; ++j) {
            float2 f0 = __half22float2(h0[j]);
            float2 f1 = __half22float2(h1[j]);
            float2 f2 = __half22float2(h2[j]);
            float2 f3 = __half22float2(h3[j]);
            a[2 * j]     = fmaf(ex0, f0.x, fmaf(ex1, f1.x, fmaf(ex2, f2.x, fmaf(ex3, f3.x, a[2 * j]))));
            a[2 * j + 1] = fmaf(ex0, f0.y, fmaf(ex1, f1.y, fmaf(ex2, f2.y, fmaf(ex3, f3.y, a[2 * j + 1]))));
        }
    }
    for (; i < deg; ++i) {
        const int b0 = p * NN + __ldg(&sp[i]);
        const float x0 = __ldg(&g_el[b0 * HH + hh]) + er_h;
        const uint4 v0 = __ldg(&fb[b0 * 32 + lane]);
        const float ex0 = __expf(fmaxf(x0, 0.2f * x0));
        den += ex0;
        const __half2* h0 = (const __half2*)&v0;
#pragma unroll
        for (int j = 0; j < 4; ++j) {
            float2 f0 = __half22float2(h0[j]);
            a[2 * j]     = fmaf(ex0, f0.x, a[2 * j]);
            a[2 * j + 1] = fmaf(ex0, f0.y, a[2 * j + 1]);
        }
    }

    const float inv = den > 0.f ? 1.f / den : 0.f;
#pragma unroll
    for (int j = 0; j < 8; ++j) {
        float v = a[j] * inv;
        a[j] = v > 0.f ? v : expm1f(v);
    }
    uint4 pk;
    __half2* ph = (__half2*)&pk;
    ph[0] = __floats2half2_rn(a[0], a[1]);
    ph[1] = __floats2half2_rn(a[2], a[3]);
    ph[2] = __floats2half2_rn(a[4], a[5]);
    ph[3] = __floats2half2_rn(a[6], a[7]);
    __stcs((uint4*)(g_outh + (long)pn * HD + lane * 8), pk);
}

// ---------------- final: out = z @ sem_w + sem_b via fp16 MMA + ldmatrix ------
__global__ void k_sem(const float* __restrict__ sb, float* __restrict__ out)
{
    __shared__ __half Zs[128][40];
    __shared__ __half Wt[128][40];
    const int nb = blockIdx.x * 128;
    const int t  = threadIdx.x, warp = t >> 5, lane = t & 31;
    const int g  = lane >> 2, tg = lane & 3;
    const int rw = warp >> 1, cw = warp & 1;

    float acc[2][8][4];
#pragma unroll
    for (int mt = 0; mt < 2; ++mt)
#pragma unroll
        for (int nt = 0; nt < 8; ++nt)
#pragma unroll
            for (int j = 0; j < 4; ++j) acc[mt][nt][j] = 0.f;

    const int arow_l = ((lane >> 3) & 1) * 8 + (lane & 7);
    const uint32_t ka = (lane >> 4) * 8;
    const uint32_t a_base0 = sm32(&Zs[rw * 32 + arow_l][ka]);
    const uint32_t a_base1 = sm32(&Zs[rw * 32 + 16 + arow_l][ka]);
    const int bn = ((lane >> 4) & 1) * 8 + (lane & 7);
    const uint32_t kb = ((lane >> 3) & 1) * 8;
    uint32_t b_base[4];
#pragma unroll
    for (int q = 0; q < 4; ++q)
        b_base[q] = sm32(&Wt[cw * 64 + q * 16 + bn][kb]);

    for (int k0 = 0; k0 < KTOT; k0 += 32) {
        const int p  = k0 >> 8;
        const int c0 = k0 & 255;
        __syncthreads();
        for (int i = t; i < 512; i += 256) {
            int r = i >> 2, q = i & 3;
            int row = nb + r;
            uint4 v = make_uint4(0u, 0u, 0u, 0u);
            if (row < NN)
                v = __ldcs((const uint4*)(g_outh + ((long)p * NN + row) * HD + c0 + q * 8));
            *(uint4*)&Zs[r][q * 8] = v;
        }
        for (int i = t; i < 512; i += 256) {
            int c = i >> 2, q = i & 3;
            *(uint4*)&Wt[c][q * 8] = *(const uint4*)(g_swt + (long)c * KTOT + k0 + q * 8);
        }
        __syncthreads();
#pragma unroll
        for (int ks = 0; ks < 2; ++ks) {
            uint32_t a0[4], a1[4], bq[4][4];
            ldm4(a0, a_base0 + ks * 32);
            ldm4(a1, a_base1 + ks * 32);
#pragma unroll
            for (int q = 0; q < 4; ++q) ldm4(bq[q], b_base[q] + ks * 32);
#pragma unroll
            for (int q = 0; q < 4; ++q) {
                mma16(acc[0][2 * q],     a0, bq[q][0], bq[q][1]);
                mma16(acc[0][2 * q + 1], a0, bq[q][2], bq[q][3]);
                mma16(acc[1][2 * q],     a1, bq[q][0], bq[q][1]);
                mma16(acc[1][2 * q + 1], a1, bq[q][2], bq[q][3]);
            }
        }
    }

#pragma unroll
    for (int mt = 0; mt < 2; ++mt) {
        const int row0 = nb + rw * 32 + mt * 16 + g, row1 = row0 + 8;
#pragma unroll
        for (int nt = 0; nt < 8; ++nt) {
            const int col = cw * 64 + nt * 8 + 2 * tg;
            const float b0v = sb[col], b1v = sb[col + 1];
            if (row0 < NN) {
                out[(long)row0 * EMB + col]     = acc[mt][nt][0] + b0v;
                out[(long)row0 * EMB + col + 1] = acc[mt][nt][1] + b1v;
            }
            if (row1 < NN) {
                out[(long)row1 * EMB + col]     = acc[mt][nt][2] + b0v;
                out[(long)row1 * EMB + col + 1] = acc[mt][nt][3] + b1v;
            }
        }
    }
}

// ---------------- launch ------------------------------------------------------
extern "C" void kernel_launch(void* const* d_in, const int* in_sizes, int n_in,
                              void* d_out, int out_size)
{
    const float* h   = (const float*)d_in[0];
    const int*   ei  = (const int*)  d_in[1];
    const float* fcw = (const float*)d_in[2];
    const float* al  = (const float*)d_in[3];
    const float* ar  = (const float*)d_in[4];
    const float* sw  = (const float*)d_in[5];
    const float* sb  = (const float*)d_in[6];
    float* out = (float*)d_out;

    k_feat  <<<2590, 256>>>(h, fcw, sw);           // 1 (feat + sw transpose + deg zero)
    k_hscat <<<dim3(EE / 256, PP), 256>>>(ei);     // 2
    k_elr   <<<PN / 8, 256>>>(al, ar);             // 3
    k_agg   <<<dim3(NN / 8, PP), 256>>>();         // 4  <- PROFILED
    k_sem   <<<(NN + 127) / 128, 256>>>(sb, out);  // 5
}